// round 2
// baseline (speedup 1.0000x reference)
#include <cuda_runtime.h>
#include <math.h>

// Problem constants
#define NB 32      // batch
#define NS 2048    // sequence
#define NE 1024    // encoder hidden
#define NP 1024    // out dim (p)
#define FAN 2048   // attn_w row length

// Scratch (device globals; no allocation allowed)
__device__ float g_hp[NB * NP];                 // h_proj + bias
__device__ float g_part[16 * NB * NS];          // per p-block partial logits (4 MB)
__device__ float g_att[NB * NS];                // softmax weights
__device__ float g_wpart[16 * NB * NE];         // per s-chunk partial weighted (2 MB)

// ---------------------------------------------------------------------------
// Kernel 1: hp[b,p] = sum_o hidden[b,o] * attn_w[p,o] + attn_b[p]
// One block per p. Block loads w row into smem, each thread accumulates all 32 b.
// ---------------------------------------------------------------------------
__global__ void __launch_bounds__(256) setup_kernel(
    const float* __restrict__ hidden,
    const float* __restrict__ attn_w,
    const float* __restrict__ attn_b)
{
    int p = blockIdx.x;
    int tid = threadIdx.x;
    int lane = tid & 31, wid = tid >> 5;

    __shared__ float ws[NE];
    __shared__ float warp_part[NB][8];

    for (int o = tid; o < NE; o += 256) ws[o] = attn_w[(size_t)p * FAN + o];
    __syncthreads();

    float acc[NB];
#pragma unroll
    for (int b = 0; b < NB; b++) acc[b] = 0.f;

    for (int o = tid; o < NE; o += 256) {
        float w = ws[o];
#pragma unroll
        for (int b = 0; b < NB; b++) acc[b] += hidden[b * NE + o] * w;
    }

#pragma unroll
    for (int b = 0; b < NB; b++) {
        float s = acc[b];
#pragma unroll
        for (int off = 16; off; off >>= 1) s += __shfl_down_sync(0xffffffffu, s, off);
        if (lane == 0) warp_part[b][wid] = s;
    }
    __syncthreads();

    if (tid < NB) {
        float s = 0.f;
#pragma unroll
        for (int w = 0; w < 8; w++) s += warp_part[tid][w];
        g_hp[tid * NP + p] = s + attn_b[p];
    }
}

// ---------------------------------------------------------------------------
// Kernel 2 (dominant): fused energy GEMM + tanh + v-dot.
// Block = 64 s-rows x 64 p-cols, K=1024 over e.  256 threads, 4x4 per thread.
// Epilogue: rowsum[s] = sum_p tanh(acc + hp[b,p]) * v[p] for this p-block,
// written to g_part[pblk][b][s]  (unique writer per element -> deterministic).
// ---------------------------------------------------------------------------
#define TM 64
#define TN 64
#define KB 16

__global__ void __launch_bounds__(256) energy_kernel(
    const float* __restrict__ enc,     // (S, B, E)
    const float* __restrict__ attn_w,  // (P, FAN); w_e = cols [1024,2048)
    const float* __restrict__ v)
{
    __shared__ float As[KB][TM];
    __shared__ float Bs[KB][TN];

    const int pblk = blockIdx.x;
    const int b    = blockIdx.z;
    const int s0   = blockIdx.y * TM;
    const int p0   = pblk * TN;

    const int tid = threadIdx.x;
    const int tx = tid & 15;      // p dimension
    const int ty = tid >> 4;      // s dimension

    // staging assignment: each thread loads one float4 per tile
    const int lrow = tid >> 2;          // 0..63
    const int lkq  = (tid & 3) * 4;     // 0,4,8,12

    const float* encBase = enc + ((size_t)(s0 + lrow) * NB + b) * NE + lkq;
    const float* wBase   = attn_w + (size_t)(p0 + lrow) * FAN + NE + lkq;

    float acc[4][4];
#pragma unroll
    for (int i = 0; i < 4; i++)
#pragma unroll
        for (int j = 0; j < 4; j++) acc[i][j] = 0.f;

    for (int k0 = 0; k0 < NE; k0 += KB) {
        float4 av = *(const float4*)(encBase + k0);
        float4 bv = *(const float4*)(wBase + k0);
        As[lkq + 0][lrow] = av.x; As[lkq + 1][lrow] = av.y;
        As[lkq + 2][lrow] = av.z; As[lkq + 3][lrow] = av.w;
        Bs[lkq + 0][lrow] = bv.x; Bs[lkq + 1][lrow] = bv.y;
        Bs[lkq + 2][lrow] = bv.z; Bs[lkq + 3][lrow] = bv.w;
        __syncthreads();

#pragma unroll
        for (int k = 0; k < KB; k++) {
            float4 a4 = *(const float4*)&As[k][ty * 4];
            float4 b4 = *(const float4*)&Bs[k][tx * 4];
            acc[0][0] += a4.x * b4.x; acc[0][1] += a4.x * b4.y;
            acc[0][2] += a4.x * b4.z; acc[0][3] += a4.x * b4.w;
            acc[1][0] += a4.y * b4.x; acc[1][1] += a4.y * b4.y;
            acc[1][2] += a4.y * b4.z; acc[1][3] += a4.y * b4.w;
            acc[2][0] += a4.z * b4.x; acc[2][1] += a4.z * b4.y;
            acc[2][2] += a4.z * b4.z; acc[2][3] += a4.z * b4.w;
            acc[3][0] += a4.w * b4.x; acc[3][1] += a4.w * b4.y;
            acc[3][2] += a4.w * b4.z; acc[3][3] += a4.w * b4.w;
        }
        __syncthreads();
    }

    // Epilogue: tanh + v weighting + reduce over the 64 p in this block
    float hv[4], vv[4];
#pragma unroll
    for (int j = 0; j < 4; j++) {
        hv[j] = g_hp[b * NP + p0 + tx * 4 + j];
        vv[j] = v[p0 + tx * 4 + j];
    }

    float rsum[4];
#pragma unroll
    for (int i = 0; i < 4; i++) {
        float s = 0.f;
#pragma unroll
        for (int j = 0; j < 4; j++)
            s += tanhf(acc[i][j] + hv[j]) * vv[j];
        rsum[i] = s;
    }

    // reduce across the 16 tx threads (contiguous lanes within half-warps)
#pragma unroll
    for (int off = 8; off; off >>= 1) {
#pragma unroll
        for (int i = 0; i < 4; i++)
            rsum[i] += __shfl_down_sync(0xffffffffu, rsum[i], off, 16);
    }

    if (tx == 0) {
#pragma unroll
        for (int i = 0; i < 4; i++)
            g_part[((size_t)pblk * NB + b) * NS + s0 + ty * 4 + i] = rsum[i];
    }
}

// ---------------------------------------------------------------------------
// Kernel 3: sum the 16 p-block partials -> logits; softmax over S per b.
// ---------------------------------------------------------------------------
__global__ void __launch_bounds__(256) softmax_kernel()
{
    int b = blockIdx.x;
    int tid = threadIdx.x;
    int lane = tid & 31, wid = tid >> 5;
    __shared__ float redm[8];
    __shared__ float reds[8];

    float vals[8];
    float m = -1e30f;
#pragma unroll
    for (int i = 0; i < 8; i++) {
        int s = tid + i * 256;
        float a = 0.f;
#pragma unroll
        for (int c = 0; c < 16; c++)
            a += g_part[((size_t)c * NB + b) * NS + s];
        vals[i] = a;
        m = fmaxf(m, a);
    }
#pragma unroll
    for (int off = 16; off; off >>= 1) m = fmaxf(m, __shfl_xor_sync(0xffffffffu, m, off));
    if (lane == 0) redm[wid] = m;
    __syncthreads();
    float bmax = redm[0];
#pragma unroll
    for (int w = 1; w < 8; w++) bmax = fmaxf(bmax, redm[w]);

    float ssum = 0.f;
#pragma unroll
    for (int i = 0; i < 8; i++) {
        vals[i] = expf(vals[i] - bmax);
        ssum += vals[i];
    }
#pragma unroll
    for (int off = 16; off; off >>= 1) ssum += __shfl_xor_sync(0xffffffffu, ssum, off);
    if (lane == 0) reds[wid] = ssum;
    __syncthreads();
    float tot = 0.f;
#pragma unroll
    for (int w = 0; w < 8; w++) tot += reds[w];
    float inv = 1.f / tot;

#pragma unroll
    for (int i = 0; i < 8; i++)
        g_att[b * NS + tid + i * 256] = vals[i] * inv;
}

// ---------------------------------------------------------------------------
// Kernel 4: weighted partials: for each (s-chunk of 128, b) block, accumulate
// sum_s a[b,s]*enc[s,b,:] into g_wpart[chunk][b][:].  Fully coalesced float4.
// ---------------------------------------------------------------------------
__global__ void __launch_bounds__(256) weighted_kernel(const float* __restrict__ enc)
{
    const int chunk = blockIdx.x;   // 0..15 (128 s each)
    const int b = blockIdx.y;
    const int tid = threadIdx.x;

    __shared__ float aw[128];
    if (tid < 128) aw[tid] = g_att[b * NS + chunk * 128 + tid];
    __syncthreads();

    const float4* base = (const float4*)enc +
                         ((size_t)(chunk * 128) * NB + b) * (NE / 4) + tid;
    const size_t rowStride = (size_t)NB * NE / 4;  // 8192 float4s

    float4 acc = make_float4(0.f, 0.f, 0.f, 0.f);
#pragma unroll 4
    for (int s = 0; s < 128; s++) {
        float w = aw[s];
        float4 x = base[(size_t)s * rowStride];
        acc.x += w * x.x; acc.y += w * x.y;
        acc.z += w * x.z; acc.w += w * x.w;
    }

    float4* o = (float4*)&g_wpart[((size_t)chunk * NB + b) * NE] + tid;
    *o = acc;
}

// ---------------------------------------------------------------------------
// Kernel 5: reduce the 16 s-chunk partials into d_out (deterministic, no atomics)
// ---------------------------------------------------------------------------
__global__ void __launch_bounds__(256) reduce_kernel(float* __restrict__ out)
{
    int idx = blockIdx.x * 256 + threadIdx.x;  // 0..32767
    float acc = 0.f;
#pragma unroll
    for (int c = 0; c < 16; c++)
        acc += g_wpart[(size_t)c * (NB * NE) + idx];
    out[idx] = acc;
}

// ---------------------------------------------------------------------------
extern "C" void kernel_launch(void* const* d_in, const int* in_sizes, int n_in,
                              void* d_out, int out_size)
{
    const float* hidden = (const float*)d_in[0];   // (32, 1024)
    const float* enc    = (const float*)d_in[1];   // (2048, 32, 1024)
    const float* attn_w = (const float*)d_in[2];   // (1024, 2048)
    const float* attn_b = (const float*)d_in[3];   // (1024,)
    const float* v      = (const float*)d_in[4];   // (1024,)
    float* out = (float*)d_out;                    // (32, 1024)

    setup_kernel<<<NP, 256>>>(hidden, attn_w, attn_b);
    energy_kernel<<<dim3(NP / TN, NS / TM, NB), 256>>>(enc, attn_w, v);
    softmax_kernel<<<NB, 256>>>();
    weighted_kernel<<<dim3(16, NB), 256>>>(enc);
    reduce_kernel<<<(NB * NE) / 256, 256>>>(out);
}

// round 5
// speedup vs baseline: 2.4524x; 2.4524x over previous
#include <cuda_runtime.h>
#include <cuda_bf16.h>
#include <cstdint>
#include <math.h>

// Problem constants
#define NB 32      // batch
#define NS 2048    // sequence
#define NE 1024    // encoder hidden
#define NP 1024    // out dim (p)
#define FAN 2048   // attn_w row length

#define NROWS (NS * NB)           // 65536 flattened (s,b) rows
#define MT 128                    // rows per CTA
#define NHALF 512                 // p-cols per CTA (2 halves)
#define NBLK 128                  // p-cols per n-block
#define KC 64                     // K chunk (bf16)
#define NKCHUNK (NE / KC)         // 16
#define ROWB 144                  // padded smem row bytes (64 bf16 + 8 pad)

// SMEM layout (dynamic)
#define SM_AH 0
#define SM_AL (SM_AH + MT * ROWB)           // 18432
#define SM_BH (SM_AL + MT * ROWB)           // 36864
#define SM_BL (SM_BH + NBLK * ROWB)         // 55296
#define SM_HP (SM_BL + NBLK * ROWB)         // 73728  (32 b x 128 p floats)
#define SM_V  (SM_HP + NB * NBLK * 4)       // 90112  (128 floats)
#define SM_RED (SM_V + NBLK * 4)            // 90624  (4 x 128 floats)
#define SM_DYN (SM_RED + 4 * MT * 4)        // 92672

// ---------------------------------------------------------------------------
// Scratch (device globals; no allocation allowed)
// ---------------------------------------------------------------------------
__device__ float g_hp[NB * NP];                       // h_proj + bias
__device__ float g_part[2 * NB * NS];                 // per p-half partial logits
__device__ float g_att[NB * NS];                      // softmax weights
__device__ float g_wpart[16 * NB * NE];               // per s-chunk partial weighted

__device__ __nv_bfloat16 g_enc_hi[(size_t)NS * NB * NE];   // 128 MB
__device__ __nv_bfloat16 g_enc_lo[(size_t)NS * NB * NE];   // 128 MB
__device__ __nv_bfloat16 g_w_hi[NP * NE];                  // 2 MB
__device__ __nv_bfloat16 g_w_lo[NP * NE];                  // 2 MB

// ---------------------------------------------------------------------------
// PTX helpers (sm_100-safe: ldmatrix + mma.sync only, NO tcgen05)
// ---------------------------------------------------------------------------
__device__ __forceinline__ uint32_t smem_u32(const void* p) {
    uint32_t a;
    asm("{ .reg .u64 t; cvta.to.shared.u64 t, %1; cvt.u32.u64 %0, t; }" : "=r"(a) : "l"(p));
    return a;
}

__device__ __forceinline__ void ldsm_x4(uint32_t& r0, uint32_t& r1, uint32_t& r2,
                                        uint32_t& r3, uint32_t addr) {
    asm volatile("ldmatrix.sync.aligned.m8n8.x4.shared.b16 {%0,%1,%2,%3}, [%4];"
                 : "=r"(r0), "=r"(r1), "=r"(r2), "=r"(r3) : "r"(addr));
}
__device__ __forceinline__ void ldsm_x2(uint32_t& r0, uint32_t& r1, uint32_t addr) {
    asm volatile("ldmatrix.sync.aligned.m8n8.x2.shared.b16 {%0,%1}, [%2];"
                 : "=r"(r0), "=r"(r1) : "r"(addr));
}
__device__ __forceinline__ void mma16816(float* c,
                                         uint32_t a0, uint32_t a1, uint32_t a2, uint32_t a3,
                                         uint32_t b0, uint32_t b1) {
    asm volatile(
        "mma.sync.aligned.m16n8k16.row.col.f32.bf16.bf16.f32 "
        "{%0,%1,%2,%3}, {%4,%5,%6,%7}, {%8,%9}, {%0,%1,%2,%3};"
        : "+f"(c[0]), "+f"(c[1]), "+f"(c[2]), "+f"(c[3])
        : "r"(a0), "r"(a1), "r"(a2), "r"(a3), "r"(b0), "r"(b1));
}

// ---------------------------------------------------------------------------
// Kernel 1: hp[b,p] = hidden[b,:]·attn_w[p,0:1024] + attn_b[p]   (fp32 exact)
// ---------------------------------------------------------------------------
__global__ void __launch_bounds__(256) setup_kernel(
    const float* __restrict__ hidden,
    const float* __restrict__ attn_w,
    const float* __restrict__ attn_b)
{
    int p = blockIdx.x;
    int tid = threadIdx.x;
    int lane = tid & 31, wid = tid >> 5;

    __shared__ float ws[NE];
    __shared__ float warp_part[NB][8];

    for (int o = tid; o < NE; o += 256) ws[o] = attn_w[(size_t)p * FAN + o];
    __syncthreads();

    float acc[NB];
#pragma unroll
    for (int b = 0; b < NB; b++) acc[b] = 0.f;

    for (int o = tid; o < NE; o += 256) {
        float w = ws[o];
#pragma unroll
        for (int b = 0; b < NB; b++) acc[b] += hidden[b * NE + o] * w;
    }
#pragma unroll
    for (int b = 0; b < NB; b++) {
        float s = acc[b];
#pragma unroll
        for (int off = 16; off; off >>= 1) s += __shfl_down_sync(0xffffffffu, s, off);
        if (lane == 0) warp_part[b][wid] = s;
    }
    __syncthreads();
    if (tid < NB) {
        float s = 0.f;
#pragma unroll
        for (int w = 0; w < 8; w++) s += warp_part[tid][w];
        g_hp[tid * NP + p] = s + attn_b[p];
    }
}

// ---------------------------------------------------------------------------
// Conversion: fp32 -> (hi, lo) bf16 split
// ---------------------------------------------------------------------------
__device__ __forceinline__ void split4(float4 x, uint2& hi, uint2& lo) {
    __nv_bfloat16 h0 = __float2bfloat16_rn(x.x);
    __nv_bfloat16 h1 = __float2bfloat16_rn(x.y);
    __nv_bfloat16 h2 = __float2bfloat16_rn(x.z);
    __nv_bfloat16 h3 = __float2bfloat16_rn(x.w);
    __nv_bfloat16 l0 = __float2bfloat16_rn(x.x - __bfloat162float(h0));
    __nv_bfloat16 l1 = __float2bfloat16_rn(x.y - __bfloat162float(h1));
    __nv_bfloat16 l2 = __float2bfloat16_rn(x.z - __bfloat162float(h2));
    __nv_bfloat16 l3 = __float2bfloat16_rn(x.w - __bfloat162float(h3));
    hi.x = ((uint32_t)__bfloat16_as_ushort(h1) << 16) | __bfloat16_as_ushort(h0);
    hi.y = ((uint32_t)__bfloat16_as_ushort(h3) << 16) | __bfloat16_as_ushort(h2);
    lo.x = ((uint32_t)__bfloat16_as_ushort(l1) << 16) | __bfloat16_as_ushort(l0);
    lo.y = ((uint32_t)__bfloat16_as_ushort(l3) << 16) | __bfloat16_as_ushort(l2);
}

__global__ void __launch_bounds__(256) convert_enc_kernel(const float* __restrict__ enc)
{
    size_t i = (size_t)blockIdx.x * 256 + threadIdx.x;   // float4 index
    float4 x = ((const float4*)enc)[i];
    uint2 hi, lo;
    split4(x, hi, lo);
    ((uint2*)g_enc_hi)[i] = hi;
    ((uint2*)g_enc_lo)[i] = lo;
}

__global__ void __launch_bounds__(256) convert_w_kernel(const float* __restrict__ attn_w)
{
    int i = blockIdx.x * 256 + threadIdx.x;  // float4 index into w_e (256 per row)
    int p = i >> 8;
    int q = i & 255;
    float4 x = *(const float4*)(attn_w + (size_t)p * FAN + NE + q * 4);
    uint2 hi, lo;
    split4(x, hi, lo);
    ((uint2*)g_w_hi)[p * 256 + q] = hi;
    ((uint2*)g_w_lo)[p * 256 + q] = lo;
}

// ---------------------------------------------------------------------------
// Kernel 2 (dominant): split-bf16 HMMA energy GEMM + fused tanh·v epilogue.
// A = enc viewed as 65536x1024 row-major (row = s*32+b, natural layout).
// CTA: 128 rows x 512 p (4 n-blocks of 128), K=1024 in chunks of 64.
// 8 warps (2m x 4n), warp tile 64x32, mma.m16n8k16 bf16, fp32 accum.
// 3 passes per chunk: A_hi*B_hi + A_lo*B_hi + A_hi*B_lo.
// ---------------------------------------------------------------------------
__global__ void __launch_bounds__(256, 2) energy_hmma_kernel(const float* __restrict__ v)
{
    extern __shared__ char smem[];
    const uint32_t su = smem_u32(smem);

    const int r0 = blockIdx.x * MT;          // global row base (s*32+b flat)
    const int ny = blockIdx.y;               // p half: 0 or 1
    const int tid = threadIdx.x;
    const int lane = tid & 31, wid = tid >> 5;
    const int wm = wid >> 2;                 // 0..1 (m)
    const int wn = wid & 3;                  // 0..3 (n)

    // ldmatrix per-lane invariant offsets
    const int grp = lane >> 3, lrow = lane & 7;
    uint32_t aoff[4];
#pragma unroll
    for (int mt = 0; mt < 4; mt++)
        aoff[mt] = (uint32_t)((wm * 64 + mt * 16 + lrow + ((grp & 1) << 3)) * ROWB
                              + ((grp >> 1) << 4));
    const int bl = lane & 15;
    uint32_t boff[4];
#pragma unroll
    for (int nt = 0; nt < 4; nt++)
        boff[nt] = (uint32_t)((wn * 32 + nt * 8 + (bl & 7)) * ROWB + ((bl >> 3) << 4));

    const uint4* gAH = (const uint4*)g_enc_hi;
    const uint4* gAL = (const uint4*)g_enc_lo;
    const uint4* gBH = (const uint4*)g_w_hi;
    const uint4* gBL = (const uint4*)g_w_lo;

    float* sh_hp = (float*)(smem + SM_HP);
    float* sh_v  = (float*)(smem + SM_V);
    float* sh_red = (float*)(smem + SM_RED);

    const int qr = lane >> 2, qc = lane & 3;
    float rowsum = 0.f;                      // valid for tid < 128 (row tid)

    for (int nb = 0; nb < 4; nb++) {
        const int p0 = ny * NHALF + nb * NBLK;

        // stage hp slice [32 b][128 p] and v slice
        for (int i = tid; i < NB * NBLK; i += 256) {
            int b = i >> 7, pl = i & 127;
            sh_hp[i] = g_hp[b * NP + p0 + pl];
        }
        if (tid < NBLK) sh_v[tid] = v[p0 + tid];

        float acc[4][4][4];
#pragma unroll
        for (int mt = 0; mt < 4; mt++)
#pragma unroll
            for (int nt = 0; nt < 4; nt++)
#pragma unroll
                for (int e = 0; e < 4; e++) acc[mt][nt][e] = 0.f;

        __syncthreads();   // hp/v staged; also guards sh_red reuse from prior nb

        for (int c = 0; c < NKCHUNK; c++) {
            const int cbase = c * 8;    // uint4 offset along K
            // stage A (128x64) hi/lo + B (128x64) hi/lo, padded rows
#pragma unroll
            for (int i = 0; i < 4; i++) {
                int idx = tid + i * 256;             // 0..1023
                int r = idx >> 3, cg = idx & 7;
                uint32_t so = (uint32_t)(r * ROWB + cg * 16);
                size_t ga = (size_t)(r0 + r) * 128 + cbase + cg;
                size_t gb = (size_t)(p0 + r) * 128 + cbase + cg;
                *(uint4*)(smem + SM_AH + so) = gAH[ga];
                *(uint4*)(smem + SM_AL + so) = gAL[ga];
                *(uint4*)(smem + SM_BH + so) = gBH[gb];
                *(uint4*)(smem + SM_BL + so) = gBL[gb];
            }
            __syncthreads();

            const uint32_t pa[3] = { su + SM_AH, su + SM_AL, su + SM_AH };
            const uint32_t pb[3] = { su + SM_BH, su + SM_BH, su + SM_BL };
#pragma unroll
            for (int pass = 0; pass < 3; pass++) {
                const uint32_t abase = pa[pass];
                const uint32_t bbase = pb[pass];
#pragma unroll
                for (int ks = 0; ks < 4; ks++) {
                    uint32_t a[4][4];
#pragma unroll
                    for (int mt = 0; mt < 4; mt++)
                        ldsm_x4(a[mt][0], a[mt][1], a[mt][2], a[mt][3],
                                abase + aoff[mt] + ks * 32);
                    uint32_t bfr[4][2];
#pragma unroll
                    for (int nt = 0; nt < 4; nt++)
                        ldsm_x2(bfr[nt][0], bfr[nt][1], bbase + boff[nt] + ks * 32);
#pragma unroll
                    for (int mt = 0; mt < 4; mt++)
#pragma unroll
                        for (int nt = 0; nt < 4; nt++)
                            mma16816(acc[mt][nt],
                                     a[mt][0], a[mt][1], a[mt][2], a[mt][3],
                                     bfr[nt][0], bfr[nt][1]);
                }
            }
            __syncthreads();   // mma reads done before restage
        }

        // Epilogue for this n-block: rsum over 128 p of tanh(acc + hp)*v
#pragma unroll
        for (int mt = 0; mt < 4; mt++) {
            int row0 = wm * 64 + mt * 16 + qr;       // local row (0..127)
            int b0 = row0 & 31, b1 = (row0 + 8) & 31;
            float s0 = 0.f, s1 = 0.f;
#pragma unroll
            for (int nt = 0; nt < 4; nt++) {
                int pl = wn * 32 + nt * 8 + qc * 2;
                float v0 = sh_v[pl], v1 = sh_v[pl + 1];
                s0 += tanhf(acc[mt][nt][0] + sh_hp[b0 * 128 + pl]) * v0
                    + tanhf(acc[mt][nt][1] + sh_hp[b0 * 128 + pl + 1]) * v1;
                s1 += tanhf(acc[mt][nt][2] + sh_hp[b1 * 128 + pl]) * v0
                    + tanhf(acc[mt][nt][3] + sh_hp[b1 * 128 + pl + 1]) * v1;
            }
            s0 += __shfl_down_sync(0xffffffffu, s0, 2, 4);
            s0 += __shfl_down_sync(0xffffffffu, s0, 1, 4);
            s1 += __shfl_down_sync(0xffffffffu, s1, 2, 4);
            s1 += __shfl_down_sync(0xffffffffu, s1, 1, 4);
            if (qc == 0) {
                sh_red[wn * MT + row0]     = s0;
                sh_red[wn * MT + row0 + 8] = s1;
            }
        }
        __syncthreads();
        if (tid < MT)
            rowsum += sh_red[tid] + sh_red[MT + tid] + sh_red[2 * MT + tid]
                    + sh_red[3 * MT + tid];
        // next nb's first __syncthreads guards sh_red reuse
    }

    if (tid < MT) {
        int grow = r0 + tid;
        int b = grow & 31;
        int s = grow >> 5;
        g_part[((size_t)ny * NB + b) * NS + s] = rowsum;
    }
}

// ---------------------------------------------------------------------------
// Kernel 3: logits = sum of 2 p-half partials; softmax over S per b.
// ---------------------------------------------------------------------------
__global__ void __launch_bounds__(256) softmax_kernel()
{
    int b = blockIdx.x;
    int tid = threadIdx.x;
    int lane = tid & 31, wid = tid >> 5;
    __shared__ float redm[8];
    __shared__ float reds[8];

    float vals[8];
    float m = -1e30f;
#pragma unroll
    for (int i = 0; i < 8; i++) {
        int s = tid + i * 256;
        float a = g_part[(size_t)b * NS + s] + g_part[((size_t)NB + b) * NS + s];
        vals[i] = a;
        m = fmaxf(m, a);
    }
#pragma unroll
    for (int off = 16; off; off >>= 1) m = fmaxf(m, __shfl_xor_sync(0xffffffffu, m, off));
    if (lane == 0) redm[wid] = m;
    __syncthreads();
    float bmax = redm[0];
#pragma unroll
    for (int w = 1; w < 8; w++) bmax = fmaxf(bmax, redm[w]);

    float ssum = 0.f;
#pragma unroll
    for (int i = 0; i < 8; i++) {
        vals[i] = expf(vals[i] - bmax);
        ssum += vals[i];
    }
#pragma unroll
    for (int off = 16; off; off >>= 1) ssum += __shfl_xor_sync(0xffffffffu, ssum, off);
    if (lane == 0) reds[wid] = ssum;
    __syncthreads();
    float tot = 0.f;
#pragma unroll
    for (int w = 0; w < 8; w++) tot += reds[w];
    float inv = 1.f / tot;

#pragma unroll
    for (int i = 0; i < 8; i++)
        g_att[b * NS + tid + i * 256] = vals[i] * inv;
}

// ---------------------------------------------------------------------------
// Kernel 4: weighted partials per (s-chunk of 128, b)
// ---------------------------------------------------------------------------
__global__ void __launch_bounds__(256) weighted_kernel(const float* __restrict__ enc)
{
    const int chunk = blockIdx.x;
    const int b = blockIdx.y;
    const int tid = threadIdx.x;

    __shared__ float aw[128];
    if (tid < 128) aw[tid] = g_att[b * NS + chunk * 128 + tid];
    __syncthreads();

    const float4* base = (const float4*)enc +
                         ((size_t)(chunk * 128) * NB + b) * (NE / 4) + tid;
    const size_t rowStride = (size_t)NB * NE / 4;

    float4 acc = make_float4(0.f, 0.f, 0.f, 0.f);
#pragma unroll 4
    for (int s = 0; s < 128; s++) {
        float w = aw[s];
        float4 x = base[(size_t)s * rowStride];
        acc.x += w * x.x; acc.y += w * x.y;
        acc.z += w * x.z; acc.w += w * x.w;
    }
    float4* o = (float4*)&g_wpart[((size_t)chunk * NB + b) * NE] + tid;
    *o = acc;
}

// ---------------------------------------------------------------------------
// Kernel 5: reduce 16 s-chunk partials -> out
// ---------------------------------------------------------------------------
__global__ void __launch_bounds__(256) reduce_kernel(float* __restrict__ out)
{
    int idx = blockIdx.x * 256 + threadIdx.x;
    float acc = 0.f;
#pragma unroll
    for (int c = 0; c < 16; c++)
        acc += g_wpart[(size_t)c * (NB * NE) + idx];
    out[idx] = acc;
}

// ---------------------------------------------------------------------------
extern "C" void kernel_launch(void* const* d_in, const int* in_sizes, int n_in,
                              void* d_out, int out_size)
{
    const float* hidden = (const float*)d_in[0];   // (32, 1024)
    const float* enc    = (const float*)d_in[1];   // (2048, 32, 1024)
    const float* attn_w = (const float*)d_in[2];   // (1024, 2048)
    const float* attn_b = (const float*)d_in[3];   // (1024,)
    const float* v      = (const float*)d_in[4];   // (1024,)
    float* out = (float*)d_out;                    // (32, 1024)

    cudaFuncSetAttribute(energy_hmma_kernel,
                         cudaFuncAttributeMaxDynamicSharedMemorySize, SM_DYN);

    setup_kernel<<<NP, 256>>>(hidden, attn_w, attn_b);
    convert_w_kernel<<<(NP * NE / 4) / 256, 256>>>(attn_w);
    convert_enc_kernel<<<(int)(((size_t)NS * NB * NE / 4) / 256), 256>>>(enc);
    energy_hmma_kernel<<<dim3(NROWS / MT, 2), 256, SM_DYN>>>(v);
    softmax_kernel<<<NB, 256>>>();
    weighted_kernel<<<dim3(16, NB), 256>>>(enc);
    reduce_kernel<<<(NB * NE) / 256, 256>>>(out);
}

// round 6
// speedup vs baseline: 3.2722x; 1.3343x over previous
#include <cuda_runtime.h>
#include <cuda_bf16.h>
#include <cstdint>
#include <math.h>

// Problem constants
#define NB 32      // batch
#define NS 2048    // sequence
#define NE 1024    // encoder hidden
#define NP 1024    // out dim (p)
#define FAN 2048   // attn_w row length

#define NROWS (NS * NB)           // 65536 flattened (s,b) rows
#define MT 128                    // rows per CTA
#define NHALF 512                 // p-cols per CTA (4 n-blocks)
#define NBLK 128                  // p-cols per n-block
#define KC 32                     // K chunk (bf16) = 64 bytes/row
#define NCH (NE / KC)             // 32 chunks
#define ROWB 80                   // padded smem row: 64B data + 16B pad (conflict-free)

#define TILEB (MT * ROWB)         // 10240 per tile (A_hi/A_lo/B_hi/B_lo all 128 rows)
#define BUFB  (4 * TILEB)         // 40960 per buffer
// SMEM layout (dynamic)
#define SM_HP  (2 * BUFB)                   // 81920  (32 b x 128 p floats)
#define SM_V   (SM_HP + NB * NBLK * 4)      // 98304  (128 floats)
#define SM_RED (SM_V + NBLK * 4)            // 98816  (4 x 128 floats)
#define SM_DYN (SM_RED + 4 * MT * 4)        // 100864

// ---------------------------------------------------------------------------
// Scratch (device globals; no allocation allowed)
// ---------------------------------------------------------------------------
__device__ float g_hp[NB * NP];                       // h_proj + bias
__device__ float g_part[2 * NB * NS];                 // per p-half partial logits
__device__ float g_att[NB * NS];                      // softmax weights
__device__ float g_wpart[16 * NB * NE];               // per s-chunk partial weighted

__device__ __nv_bfloat16 g_enc_hi[(size_t)NS * NB * NE];   // 128 MB
__device__ __nv_bfloat16 g_enc_lo[(size_t)NS * NB * NE];   // 128 MB
__device__ __nv_bfloat16 g_w_hi[NP * NE];                  // 2 MB
__device__ __nv_bfloat16 g_w_lo[NP * NE];                  // 2 MB

// ---------------------------------------------------------------------------
// PTX helpers (sm_100-safe: ldmatrix + mma.sync + cp.async, NO tcgen05)
// ---------------------------------------------------------------------------
__device__ __forceinline__ uint32_t smem_u32(const void* p) {
    uint32_t a;
    asm("{ .reg .u64 t; cvta.to.shared.u64 t, %1; cvt.u32.u64 %0, t; }" : "=r"(a) : "l"(p));
    return a;
}
__device__ __forceinline__ void ldsm_x4(uint32_t* r, uint32_t addr) {
    asm volatile("ldmatrix.sync.aligned.m8n8.x4.shared.b16 {%0,%1,%2,%3}, [%4];"
                 : "=r"(r[0]), "=r"(r[1]), "=r"(r[2]), "=r"(r[3]) : "r"(addr));
}
__device__ __forceinline__ void mma16816(float* c,
                                         uint32_t a0, uint32_t a1, uint32_t a2, uint32_t a3,
                                         uint32_t b0, uint32_t b1) {
    asm volatile(
        "mma.sync.aligned.m16n8k16.row.col.f32.bf16.bf16.f32 "
        "{%0,%1,%2,%3}, {%4,%5,%6,%7}, {%8,%9}, {%0,%1,%2,%3};"
        : "+f"(c[0]), "+f"(c[1]), "+f"(c[2]), "+f"(c[3])
        : "r"(a0), "r"(a1), "r"(a2), "r"(a3), "r"(b0), "r"(b1));
}
__device__ __forceinline__ void cp16(uint32_t dst, const void* src) {
    asm volatile("cp.async.cg.shared.global [%0], [%1], 16;" :: "r"(dst), "l"(src));
}
#define CP_COMMIT() asm volatile("cp.async.commit_group;" ::: "memory")
#define CP_WAIT1()  asm volatile("cp.async.wait_group 1;" ::: "memory")

// ---------------------------------------------------------------------------
// Kernel 1: hp[b,p] = hidden[b,:]·attn_w[p,0:1024] + attn_b[p]   (fp32 exact)
// ---------------------------------------------------------------------------
__global__ void __launch_bounds__(256) setup_kernel(
    const float* __restrict__ hidden,
    const float* __restrict__ attn_w,
    const float* __restrict__ attn_b)
{
    int p = blockIdx.x;
    int tid = threadIdx.x;
    int lane = tid & 31, wid = tid >> 5;

    __shared__ float ws[NE];
    __shared__ float warp_part[NB][8];

    for (int o = tid; o < NE; o += 256) ws[o] = attn_w[(size_t)p * FAN + o];
    __syncthreads();

    float acc[NB];
#pragma unroll
    for (int b = 0; b < NB; b++) acc[b] = 0.f;

    for (int o = tid; o < NE; o += 256) {
        float w = ws[o];
#pragma unroll
        for (int b = 0; b < NB; b++) acc[b] += hidden[b * NE + o] * w;
    }
#pragma unroll
    for (int b = 0; b < NB; b++) {
        float s = acc[b];
#pragma unroll
        for (int off = 16; off; off >>= 1) s += __shfl_down_sync(0xffffffffu, s, off);
        if (lane == 0) warp_part[b][wid] = s;
    }
    __syncthreads();
    if (tid < NB) {
        float s = 0.f;
#pragma unroll
        for (int w = 0; w < 8; w++) s += warp_part[tid][w];
        g_hp[tid * NP + p] = s + attn_b[p];
    }
}

// ---------------------------------------------------------------------------
// Conversion: fp32 -> (hi, lo) bf16 split
// ---------------------------------------------------------------------------
__device__ __forceinline__ void split4(float4 x, uint2& hi, uint2& lo) {
    __nv_bfloat16 h0 = __float2bfloat16_rn(x.x);
    __nv_bfloat16 h1 = __float2bfloat16_rn(x.y);
    __nv_bfloat16 h2 = __float2bfloat16_rn(x.z);
    __nv_bfloat16 h3 = __float2bfloat16_rn(x.w);
    __nv_bfloat16 l0 = __float2bfloat16_rn(x.x - __bfloat162float(h0));
    __nv_bfloat16 l1 = __float2bfloat16_rn(x.y - __bfloat162float(h1));
    __nv_bfloat16 l2 = __float2bfloat16_rn(x.z - __bfloat162float(h2));
    __nv_bfloat16 l3 = __float2bfloat16_rn(x.w - __bfloat162float(h3));
    hi.x = ((uint32_t)__bfloat16_as_ushort(h1) << 16) | __bfloat16_as_ushort(h0);
    hi.y = ((uint32_t)__bfloat16_as_ushort(h3) << 16) | __bfloat16_as_ushort(h2);
    lo.x = ((uint32_t)__bfloat16_as_ushort(l1) << 16) | __bfloat16_as_ushort(l0);
    lo.y = ((uint32_t)__bfloat16_as_ushort(l3) << 16) | __bfloat16_as_ushort(l2);
}

__global__ void __launch_bounds__(256) convert_enc_kernel(const float* __restrict__ enc)
{
    size_t i = (size_t)blockIdx.x * 256 + threadIdx.x;   // float4 index
    float4 x = ((const float4*)enc)[i];
    uint2 hi, lo;
    split4(x, hi, lo);
    ((uint2*)g_enc_hi)[i] = hi;
    ((uint2*)g_enc_lo)[i] = lo;
}

__global__ void __launch_bounds__(256) convert_w_kernel(const float* __restrict__ attn_w)
{
    int i = blockIdx.x * 256 + threadIdx.x;  // float4 index into w_e (256 per row)
    int p = i >> 8;
    int q = i & 255;
    float4 x = *(const float4*)(attn_w + (size_t)p * FAN + NE + q * 4);
    uint2 hi, lo;
    split4(x, hi, lo);
    ((uint2*)g_w_hi)[p * 256 + q] = hi;
    ((uint2*)g_w_lo)[p * 256 + q] = lo;
}

// ---------------------------------------------------------------------------
// Kernel 2 (dominant): split-bf16 HMMA energy GEMM, cp.async double-buffered,
// fragment-reuse across the 3 precision passes, fused tanh·v epilogue.
// CTA: 128 rows x 512 p (4 n-blocks of 128). 8 warps (2m x 4n), warp 64x32.
// ---------------------------------------------------------------------------
__global__ void __launch_bounds__(256, 2) energy_hmma_kernel(const float* __restrict__ v)
{
    extern __shared__ char smem[];
    const uint32_t su = smem_u32(smem);

    const int r0 = blockIdx.x * MT;          // global row base (s*32+b flat)
    const int ny = blockIdx.y;               // p half: 0 or 1
    const int tid = threadIdx.x;
    const int lane = tid & 31, wid = tid >> 5;
    const int wm = wid >> 2;                 // 0..1 (m)
    const int wn = wid & 3;                  // 0..3 (n)

    // ldmatrix per-lane offsets (within a tile, ROWB-padded rows)
    const int grp = lane >> 3, lrow = lane & 7;
    uint32_t aoff[4];
#pragma unroll
    for (int mt = 0; mt < 4; mt++)
        aoff[mt] = (uint32_t)((wm * 64 + mt * 16 + lrow + ((grp & 1) << 3)) * ROWB
                              + ((grp >> 1) << 4));
    uint32_t boff[2];
#pragma unroll
    for (int ntp = 0; ntp < 2; ntp++)
        boff[ntp] = (uint32_t)((wn * 32 + ntp * 16 + ((grp >> 1) << 3) + lrow) * ROWB
                               + ((grp & 1) << 4));

    const uint4* gAH = (const uint4*)g_enc_hi;
    const uint4* gAL = (const uint4*)g_enc_lo;
    const uint4* gBH = (const uint4*)g_w_hi;
    const uint4* gBL = (const uint4*)g_w_lo;

    float* sh_hp  = (float*)(smem + SM_HP);
    float* sh_v   = (float*)(smem + SM_V);
    float* sh_red = (float*)(smem + SM_RED);

    // staging constants: i even -> j = tid, i odd -> j = tid + 256
    const int r_e = tid >> 2, cg = tid & 3;
    const int r_o = r_e + 64;
    const uint32_t so_e = (uint32_t)(r_e * ROWB + cg * 16);
    const uint32_t so_o = (uint32_t)(r_o * ROWB + cg * 16);

    const int qr = lane >> 2, qc = lane & 3;
    float rowsum = 0.f;                      // valid for tid < 128

    for (int nb = 0; nb < 4; nb++) {
        const int p0 = ny * NHALF + nb * NBLK;

        // stage hp slice [32 b][128 p] and v slice (plain stores; ordered by
        // the first loop __syncthreads below)
        for (int i = tid; i < NB * NBLK; i += 256) {
            int b = i >> 7, pl = i & 127;
            sh_hp[i] = g_hp[b * NP + p0 + pl];
        }
        if (tid < NBLK) sh_v[tid] = v[p0 + tid];

        float acc[4][4][4];
#pragma unroll
        for (int mt = 0; mt < 4; mt++)
#pragma unroll
            for (int nt = 0; nt < 4; nt++)
#pragma unroll
                for (int e = 0; e < 4; e++) acc[mt][nt][e] = 0.f;

        // cp.async staging of one chunk into buffer (c & 1)
        auto stage = [&](int c) {
            const uint32_t bufbase = su + (uint32_t)(c & 1) * BUFB;
            const int cb = c * 4;   // uint4 offset along K
            // tile 0: A_hi, 1: A_lo, 2: B_hi, 3: B_lo
            cp16(bufbase + 0 * TILEB + so_e, gAH + (size_t)(r0 + r_e) * 128 + cb + cg);
            cp16(bufbase + 0 * TILEB + so_o, gAH + (size_t)(r0 + r_o) * 128 + cb + cg);
            cp16(bufbase + 1 * TILEB + so_e, gAL + (size_t)(r0 + r_e) * 128 + cb + cg);
            cp16(bufbase + 1 * TILEB + so_o, gAL + (size_t)(r0 + r_o) * 128 + cb + cg);
            cp16(bufbase + 2 * TILEB + so_e, gBH + (size_t)(p0 + r_e) * 128 + cb + cg);
            cp16(bufbase + 2 * TILEB + so_o, gBH + (size_t)(p0 + r_o) * 128 + cb + cg);
            cp16(bufbase + 3 * TILEB + so_e, gBL + (size_t)(p0 + r_e) * 128 + cb + cg);
            cp16(bufbase + 3 * TILEB + so_o, gBL + (size_t)(p0 + r_o) * 128 + cb + cg);
        };

        stage(0); CP_COMMIT();
        stage(1); CP_COMMIT();

        for (int c = 0; c < NCH; c++) {
            CP_WAIT1();
            __syncthreads();                  // buffer (c&1) ready for all warps

            const uint32_t base = su + (uint32_t)(c & 1) * BUFB;
#pragma unroll
            for (int ks = 0; ks < 2; ks++) {
                const uint32_t ko = (uint32_t)(ks * 32);
                uint32_t bh[2][4], bl[2][4];
#pragma unroll
                for (int ntp = 0; ntp < 2; ntp++)
                    ldsm_x4(bh[ntp], base + 2 * TILEB + boff[ntp] + ko);
#pragma unroll
                for (int ntp = 0; ntp < 2; ntp++)
                    ldsm_x4(bl[ntp], base + 3 * TILEB + boff[ntp] + ko);
#pragma unroll
                for (int mt = 0; mt < 4; mt++) {
                    uint32_t ah[4], al[4];
                    ldsm_x4(ah, base + 0 * TILEB + aoff[mt] + ko);
                    ldsm_x4(al, base + 1 * TILEB + aoff[mt] + ko);
#pragma unroll
                    for (int ntp = 0; ntp < 2; ntp++) {
                        mma16816(acc[mt][2 * ntp],     ah[0], ah[1], ah[2], ah[3],
                                 bh[ntp][0], bh[ntp][1]);
                        mma16816(acc[mt][2 * ntp + 1], ah[0], ah[1], ah[2], ah[3],
                                 bh[ntp][2], bh[ntp][3]);
                        mma16816(acc[mt][2 * ntp],     al[0], al[1], al[2], al[3],
                                 bh[ntp][0], bh[ntp][1]);
                        mma16816(acc[mt][2 * ntp + 1], al[0], al[1], al[2], al[3],
                                 bh[ntp][2], bh[ntp][3]);
                        mma16816(acc[mt][2 * ntp],     ah[0], ah[1], ah[2], ah[3],
                                 bl[ntp][0], bl[ntp][1]);
                        mma16816(acc[mt][2 * ntp + 1], ah[0], ah[1], ah[2], ah[3],
                                 bl[ntp][2], bl[ntp][3]);
                    }
                }
            }
            __syncthreads();                  // all warps done reading buffer (c&1)
            if (c + 2 < NCH) stage(c + 2);    // refill the buffer just consumed
            CP_COMMIT();                      // commit (possibly empty) group
        }

        // Epilogue for this n-block: rsum over 128 p of tanh(acc + hp)*v
#pragma unroll
        for (int mt = 0; mt < 4; mt++) {
            int row0 = wm * 64 + mt * 16 + qr;       // local row (0..127)
            int b0 = row0 & 31, b1 = (row0 + 8) & 31;
            float s0 = 0.f, s1 = 0.f;
#pragma unroll
            for (int nt = 0; nt < 4; nt++) {
                int pl = wn * 32 + nt * 8 + qc * 2;
                float v0 = sh_v[pl], v1 = sh_v[pl + 1];
                s0 += tanhf(acc[mt][nt][0] + sh_hp[b0 * 128 + pl]) * v0
                    + tanhf(acc[mt][nt][1] + sh_hp[b0 * 128 + pl + 1]) * v1;
                s1 += tanhf(acc[mt][nt][2] + sh_hp[b1 * 128 + pl]) * v0
                    + tanhf(acc[mt][nt][3] + sh_hp[b1 * 128 + pl + 1]) * v1;
            }
            s0 += __shfl_down_sync(0xffffffffu, s0, 2, 4);
            s0 += __shfl_down_sync(0xffffffffu, s0, 1, 4);
            s1 += __shfl_down_sync(0xffffffffu, s1, 2, 4);
            s1 += __shfl_down_sync(0xffffffffu, s1, 1, 4);
            if (qc == 0) {
                sh_red[wn * MT + row0]     = s0;
                sh_red[wn * MT + row0 + 8] = s1;
            }
        }
        __syncthreads();
        if (tid < MT)
            rowsum += sh_red[tid] + sh_red[MT + tid] + sh_red[2 * MT + tid]
                    + sh_red[3 * MT + tid];
        __syncthreads();   // sh_red/sh_hp safe to reuse next nb
    }

    if (tid < MT) {
        int grow = r0 + tid;
        int b = grow & 31;
        int s = grow >> 5;
        g_part[((size_t)ny * NB + b) * NS + s] = rowsum;
    }
}

// ---------------------------------------------------------------------------
// Kernel 3: logits = sum of 2 p-half partials; softmax over S per b.
// ---------------------------------------------------------------------------
__global__ void __launch_bounds__(256) softmax_kernel()
{
    int b = blockIdx.x;
    int tid = threadIdx.x;
    int lane = tid & 31, wid = tid >> 5;
    __shared__ float redm[8];
    __shared__ float reds[8];

    float vals[8];
    float m = -1e30f;
#pragma unroll
    for (int i = 0; i < 8; i++) {
        int s = tid + i * 256;
        float a = g_part[(size_t)b * NS + s] + g_part[((size_t)NB + b) * NS + s];
        vals[i] = a;
        m = fmaxf(m, a);
    }
#pragma unroll
    for (int off = 16; off; off >>= 1) m = fmaxf(m, __shfl_xor_sync(0xffffffffu, m, off));
    if (lane == 0) redm[wid] = m;
    __syncthreads();
    float bmax = redm[0];
#pragma unroll
    for (int w = 1; w < 8; w++) bmax = fmaxf(bmax, redm[w]);

    float ssum = 0.f;
#pragma unroll
    for (int i = 0; i < 8; i++) {
        vals[i] = expf(vals[i] - bmax);
        ssum += vals[i];
    }
#pragma unroll
    for (int off = 16; off; off >>= 1) ssum += __shfl_xor_sync(0xffffffffu, ssum, off);
    if (lane == 0) reds[wid] = ssum;
    __syncthreads();
    float tot = 0.f;
#pragma unroll
    for (int w = 0; w < 8; w++) tot += reds[w];
    float inv = 1.f / tot;

#pragma unroll
    for (int i = 0; i < 8; i++)
        g_att[b * NS + tid + i * 256] = vals[i] * inv;
}

// ---------------------------------------------------------------------------
// Kernel 4: weighted partials per (s-chunk of 128, b)
// ---------------------------------------------------------------------------
__global__ void __launch_bounds__(256) weighted_kernel(const float* __restrict__ enc)
{
    const int chunk = blockIdx.x;
    const int b = blockIdx.y;
    const int tid = threadIdx.x;

    __shared__ float aw[128];
    if (tid < 128) aw[tid] = g_att[b * NS + chunk * 128 + tid];
    __syncthreads();

    const float4* base = (const float4*)enc +
                         ((size_t)(chunk * 128) * NB + b) * (NE / 4) + tid;
    const size_t rowStride = (size_t)NB * NE / 4;

    float4 acc = make_float4(0.f, 0.f, 0.f, 0.f);
#pragma unroll 4
    for (int s = 0; s < 128; s++) {
        float w = aw[s];
        float4 x = base[(size_t)s * rowStride];
        acc.x += w * x.x; acc.y += w * x.y;
        acc.z += w * x.z; acc.w += w * x.w;
    }
    float4* o = (float4*)&g_wpart[((size_t)chunk * NB + b) * NE] + tid;
    *o = acc;
}

// ---------------------------------------------------------------------------
// Kernel 5: reduce 16 s-chunk partials -> out
// ---------------------------------------------------------------------------
__global__ void __launch_bounds__(256) reduce_kernel(float* __restrict__ out)
{
    int idx = blockIdx.x * 256 + threadIdx.x;
    float acc = 0.f;
#pragma unroll
    for (int c = 0; c < 16; c++)
        acc += g_wpart[(size_t)c * (NB * NE) + idx];
    out[idx] = acc;
}

// ---------------------------------------------------------------------------
extern "C" void kernel_launch(void* const* d_in, const int* in_sizes, int n_in,
                              void* d_out, int out_size)
{
    const float* hidden = (const float*)d_in[0];   // (32, 1024)
    const float* enc    = (const float*)d_in[1];   // (2048, 32, 1024)
    const float* attn_w = (const float*)d_in[2];   // (1024, 2048)
    const float* attn_b = (const float*)d_in[3];   // (1024,)
    const float* v      = (const float*)d_in[4];   // (1024,)
    float* out = (float*)d_out;                    // (32, 1024)

    cudaFuncSetAttribute(energy_hmma_kernel,
                         cudaFuncAttributeMaxDynamicSharedMemorySize, SM_DYN);

    setup_kernel<<<NP, 256>>>(hidden, attn_w, attn_b);
    convert_w_kernel<<<(NP * NE / 4) / 256, 256>>>(attn_w);
    convert_enc_kernel<<<(int)(((size_t)NS * NB * NE / 4) / 256), 256>>>(enc);
    energy_hmma_kernel<<<dim3(NROWS / MT, 2), 256, SM_DYN>>>(v);
    softmax_kernel<<<NB, 256>>>();
    weighted_kernel<<<dim3(16, NB), 256>>>(enc);
    reduce_kernel<<<(NB * NE) / 256, 256>>>(out);
}

// round 8
// speedup vs baseline: 3.8825x; 1.1865x over previous
#include <cuda_runtime.h>
#include <cuda_bf16.h>
#include <cstdint>
#include <math.h>

// Problem constants
#define NB 32      // batch
#define NS 2048    // sequence
#define NE 1024    // encoder hidden
#define NP 1024    // out dim (p)
#define FAN 2048   // attn_w row length

#define NROWS (NS * NB)           // 65536 flattened (s,b) rows
#define MT 128                    // rows per CTA
#define NHALF 512                 // p-cols per CTA (4 n-blocks)
#define NBLK 128                  // p-cols per n-block
#define KC 32                     // K chunk (bf16) = 64 bytes/row
#define NCH (NE / KC)             // 32 chunks

#define TILE 8192                 // 128 rows x 64B (swizzled, no pad)
#define BUFB (4 * TILE)           // 32768 per stage (A_hi, A_lo, B_hi, B_lo)
#define NSTAGE 3
#define SM_RED (NSTAGE * BUFB)    // 98304  (4 x 128 floats)
#define SM_DYN (SM_RED + 4 * MT * 4)   // 100352

// ---------------------------------------------------------------------------
// Scratch (device globals; no allocation allowed)
// ---------------------------------------------------------------------------
__device__ float g_hp[NB * NP];                       // h_proj + bias
__device__ float g_part[2 * NB * NS];                 // per p-half partial logits
__device__ float g_att[NB * NS];                      // softmax weights
__device__ float g_wpart[16 * NB * NE];               // per s-chunk partial weighted

__device__ __nv_bfloat16 g_enc_hi[(size_t)NS * NB * NE];   // 128 MB
__device__ __nv_bfloat16 g_enc_lo[(size_t)NS * NB * NE];   // 128 MB
__device__ __nv_bfloat16 g_w_hi[NP * NE];                  // 2 MB
__device__ __nv_bfloat16 g_w_lo[NP * NE];                  // 2 MB

// ---------------------------------------------------------------------------
// PTX helpers (sm_100-safe: ldmatrix + mma.sync + cp.async, NO tcgen05)
// ---------------------------------------------------------------------------
__device__ __forceinline__ uint32_t smem_u32(const void* p) {
    uint32_t a;
    asm("{ .reg .u64 t; cvta.to.shared.u64 t, %1; cvt.u32.u64 %0, t; }" : "=r"(a) : "l"(p));
    return a;
}
__device__ __forceinline__ void ldsm_x4(uint32_t* r, uint32_t addr) {
    asm volatile("ldmatrix.sync.aligned.m8n8.x4.shared.b16 {%0,%1,%2,%3}, [%4];"
                 : "=r"(r[0]), "=r"(r[1]), "=r"(r[2]), "=r"(r[3]) : "r"(addr));
}
__device__ __forceinline__ void mma16816(float* c,
                                         uint32_t a0, uint32_t a1, uint32_t a2, uint32_t a3,
                                         uint32_t b0, uint32_t b1) {
    asm volatile(
        "mma.sync.aligned.m16n8k16.row.col.f32.bf16.bf16.f32 "
        "{%0,%1,%2,%3}, {%4,%5,%6,%7}, {%8,%9}, {%0,%1,%2,%3};"
        : "+f"(c[0]), "+f"(c[1]), "+f"(c[2]), "+f"(c[3])
        : "r"(a0), "r"(a1), "r"(a2), "r"(a3), "r"(b0), "r"(b1));
}
__device__ __forceinline__ void cp16(uint32_t dst, const void* src) {
    asm volatile("cp.async.cg.shared.global [%0], [%1], 16;" :: "r"(dst), "l"(src));
}
#define CP_COMMIT() asm volatile("cp.async.commit_group;" ::: "memory")
#define CP_WAIT1()  asm volatile("cp.async.wait_group 1;" ::: "memory")

// Swizzled smem offset within a tile: row r (0..127), 16B segment seg (0..3).
__device__ __forceinline__ uint32_t swz(int r, int seg) {
    return (uint32_t)(r * 64 + (((seg) ^ ((r >> 1) & 3)) << 4));
}

// ---------------------------------------------------------------------------
// Kernel 1: hp[b,p] = hidden[b,:]·attn_w[p,0:1024] + attn_b[p]   (fp32 exact)
// ---------------------------------------------------------------------------
__global__ void __launch_bounds__(256) setup_kernel(
    const float* __restrict__ hidden,
    const float* __restrict__ attn_w,
    const float* __restrict__ attn_b)
{
    int p = blockIdx.x;
    int tid = threadIdx.x;
    int lane = tid & 31, wid = tid >> 5;

    __shared__ float ws[NE];
    __shared__ float warp_part[NB][8];

    for (int o = tid; o < NE; o += 256) ws[o] = attn_w[(size_t)p * FAN + o];
    __syncthreads();

    float acc[NB];
#pragma unroll
    for (int b = 0; b < NB; b++) acc[b] = 0.f;

    for (int o = tid; o < NE; o += 256) {
        float w = ws[o];
#pragma unroll
        for (int b = 0; b < NB; b++) acc[b] += hidden[b * NE + o] * w;
    }
#pragma unroll
    for (int b = 0; b < NB; b++) {
        float s = acc[b];
#pragma unroll
        for (int off = 16; off; off >>= 1) s += __shfl_down_sync(0xffffffffu, s, off);
        if (lane == 0) warp_part[b][wid] = s;
    }
    __syncthreads();
    if (tid < NB) {
        float s = 0.f;
#pragma unroll
        for (int w = 0; w < 8; w++) s += warp_part[tid][w];
        g_hp[tid * NP + p] = s + attn_b[p];
    }
}

// ---------------------------------------------------------------------------
// Conversion: fp32 -> (hi, lo) bf16 split
// ---------------------------------------------------------------------------
__device__ __forceinline__ void split4(float4 x, uint2& hi, uint2& lo) {
    __nv_bfloat16 h0 = __float2bfloat16_rn(x.x);
    __nv_bfloat16 h1 = __float2bfloat16_rn(x.y);
    __nv_bfloat16 h2 = __float2bfloat16_rn(x.z);
    __nv_bfloat16 h3 = __float2bfloat16_rn(x.w);
    __nv_bfloat16 l0 = __float2bfloat16_rn(x.x - __bfloat162float(h0));
    __nv_bfloat16 l1 = __float2bfloat16_rn(x.y - __bfloat162float(h1));
    __nv_bfloat16 l2 = __float2bfloat16_rn(x.z - __bfloat162float(h2));
    __nv_bfloat16 l3 = __float2bfloat16_rn(x.w - __bfloat162float(h3));
    hi.x = ((uint32_t)__bfloat16_as_ushort(h1) << 16) | __bfloat16_as_ushort(h0);
    hi.y = ((uint32_t)__bfloat16_as_ushort(h3) << 16) | __bfloat16_as_ushort(h2);
    lo.x = ((uint32_t)__bfloat16_as_ushort(l1) << 16) | __bfloat16_as_ushort(l0);
    lo.y = ((uint32_t)__bfloat16_as_ushort(l3) << 16) | __bfloat16_as_ushort(l2);
}

__global__ void __launch_bounds__(256) convert_enc_kernel(const float* __restrict__ enc)
{
    size_t i = (size_t)blockIdx.x * 256 + threadIdx.x;   // float4 index
    float4 x = ((const float4*)enc)[i];
    uint2 hi, lo;
    split4(x, hi, lo);
    ((uint2*)g_enc_hi)[i] = hi;
    ((uint2*)g_enc_lo)[i] = lo;
}

__global__ void __launch_bounds__(256) convert_w_kernel(const float* __restrict__ attn_w)
{
    int i = blockIdx.x * 256 + threadIdx.x;  // float4 index into w_e (256 per row)
    int p = i >> 8;
    int q = i & 255;
    float4 x = *(const float4*)(attn_w + (size_t)p * FAN + NE + q * 4);
    uint2 hi, lo;
    split4(x, hi, lo);
    ((uint2*)g_w_hi)[p * 256 + q] = hi;
    ((uint2*)g_w_lo)[p * 256 + q] = lo;
}

// ---------------------------------------------------------------------------
// Kernel 2 (dominant): split-bf16 HMMA energy GEMM, 3-stage cp.async pipeline,
// swizzled (pad-free) smem, ONE __syncthreads per chunk, fused tanh·v epilogue.
// CTA: 128 rows x 512 p (4 n-blocks of 128). 8 warps (2m x 4n), warp 64x32.
// ---------------------------------------------------------------------------
__global__ void __launch_bounds__(256, 2) energy_hmma_kernel(const float* __restrict__ v)
{
    extern __shared__ char smem[];
    const uint32_t su = smem_u32(smem);

    const int r0 = blockIdx.x * MT;          // global row base (s*32+b flat)
    const int ny = blockIdx.y;               // p half: 0 or 1
    const int tid = threadIdx.x;
    const int lane = tid & 31, wid = tid >> 5;
    const int wm = wid >> 2;                 // 0..1 (m)
    const int wn = wid & 3;                  // 0..3 (n)

    // ldmatrix per-lane row constants
    const int grp = lane >> 3, lrow = lane & 7;
    uint32_t abase[4]; int arsw[4];
#pragma unroll
    for (int mt = 0; mt < 4; mt++) {
        int row = wm * 64 + mt * 16 + lrow + ((grp & 1) << 3);
        abase[mt] = (uint32_t)(row * 64);
        arsw[mt] = (row >> 1) & 3;
    }
    const int asg = grp >> 1;                // A column-half segment bit
    uint32_t bbase[2]; int brsw[2];
#pragma unroll
    for (int ntp = 0; ntp < 2; ntp++) {
        int row = wn * 32 + ntp * 16 + ((grp >> 1) << 3) + lrow;
        bbase[ntp] = (uint32_t)(row * 64);
        brsw[ntp] = (row >> 1) & 3;
    }
    const int bsg = grp & 1;                 // B column-half segment bit

    const uint4* gAH = (const uint4*)g_enc_hi;
    const uint4* gAL = (const uint4*)g_enc_lo;
    const uint4* gBH = (const uint4*)g_w_hi;
    const uint4* gBL = (const uint4*)g_w_lo;

    float* sh_red = (float*)(smem + SM_RED);

    // staging constants: thread handles (r1, sg) and (r1+64, sg) per tile
    const int r1 = tid >> 2, sg = tid & 3;
    const int r2 = r1 + 64;
    const uint32_t so1 = swz(r1, sg);
    const uint32_t so2 = swz(r2, sg);

    const int qr = lane >> 2, qc = lane & 3;
    float rowsum = 0.f;                      // valid for tid < 128

    for (int nb = 0; nb < 4; nb++) {
        const int p0 = ny * NHALF + nb * NBLK;

        float acc[4][4][4];
#pragma unroll
        for (int mt = 0; mt < 4; mt++)
#pragma unroll
            for (int nt = 0; nt < 4; nt++)
#pragma unroll
                for (int e = 0; e < 4; e++) acc[mt][nt][e] = 0.f;

        auto stage = [&](int c) {
            const uint32_t bb = su + (uint32_t)(c % NSTAGE) * BUFB;
            const int cb = c * 4;   // uint4 offset along K
            cp16(bb + 0 * TILE + so1, gAH + (size_t)(r0 + r1) * 128 + cb + sg);
            cp16(bb + 0 * TILE + so2, gAH + (size_t)(r0 + r2) * 128 + cb + sg);
            cp16(bb + 1 * TILE + so1, gAL + (size_t)(r0 + r1) * 128 + cb + sg);
            cp16(bb + 1 * TILE + so2, gAL + (size_t)(r0 + r2) * 128 + cb + sg);
            cp16(bb + 2 * TILE + so1, gBH + (size_t)(p0 + r1) * 128 + cb + sg);
            cp16(bb + 2 * TILE + so2, gBH + (size_t)(p0 + r2) * 128 + cb + sg);
            cp16(bb + 3 * TILE + so1, gBL + (size_t)(p0 + r1) * 128 + cb + sg);
            cp16(bb + 3 * TILE + so2, gBL + (size_t)(p0 + r2) * 128 + cb + sg);
        };

        stage(0); CP_COMMIT();
        stage(1); CP_COMMIT();

        for (int c = 0; c < NCH; c++) {
            CP_WAIT1();                       // group c complete
            __syncthreads();                  // data visible; buf (c-1)%3 free
            if (c + 2 < NCH) stage(c + 2);    // writes buf (c-1)%3
            CP_COMMIT();

            const uint32_t base = su + (uint32_t)(c % NSTAGE) * BUFB;
#pragma unroll
            for (int ks = 0; ks < 2; ks++) {
                uint32_t bh[2][4], bl[2][4];
#pragma unroll
                for (int ntp = 0; ntp < 2; ntp++) {
                    const int seg = 2 * ks + bsg;
                    const uint32_t bo = bbase[ntp] + (uint32_t)((seg ^ brsw[ntp]) << 4);
                    ldsm_x4(bh[ntp], base + 2 * TILE + bo);
                    ldsm_x4(bl[ntp], base + 3 * TILE + bo);
                }
#pragma unroll
                for (int mt = 0; mt < 4; mt++) {
                    const int seg = 2 * ks + asg;
                    const uint32_t ao = abase[mt] + (uint32_t)((seg ^ arsw[mt]) << 4);
                    uint32_t ah[4], al[4];
                    ldsm_x4(ah, base + 0 * TILE + ao);
                    ldsm_x4(al, base + 1 * TILE + ao);
#pragma unroll
                    for (int ntp = 0; ntp < 2; ntp++) {
                        mma16816(acc[mt][2 * ntp],     ah[0], ah[1], ah[2], ah[3],
                                 bh[ntp][0], bh[ntp][1]);
                        mma16816(acc[mt][2 * ntp + 1], ah[0], ah[1], ah[2], ah[3],
                                 bh[ntp][2], bh[ntp][3]);
                        mma16816(acc[mt][2 * ntp],     al[0], al[1], al[2], al[3],
                                 bh[ntp][0], bh[ntp][1]);
                        mma16816(acc[mt][2 * ntp + 1], al[0], al[1], al[2], al[3],
                                 bh[ntp][2], bh[ntp][3]);
                        mma16816(acc[mt][2 * ntp],     ah[0], ah[1], ah[2], ah[3],
                                 bl[ntp][0], bl[ntp][1]);
                        mma16816(acc[mt][2 * ntp + 1], ah[0], ah[1], ah[2], ah[3],
                                 bl[ntp][2], bl[ntp][3]);
                    }
                }
            }
        }

        // Epilogue: rsum over 128 p of tanh(acc + hp)*v ; hp/v from gmem (L2)
#pragma unroll
        for (int mt = 0; mt < 4; mt++) {
            int row0 = wm * 64 + mt * 16 + qr;       // local row (0..127)
            int b0 = row0 & 31, b1 = (row0 + 8) & 31;
            float s0 = 0.f, s1 = 0.f;
#pragma unroll
            for (int nt = 0; nt < 4; nt++) {
                int pl = wn * 32 + nt * 8 + qc * 2;
                float2 v2  = *(const float2*)(v + p0 + pl);
                float2 h0c = *(const float2*)(g_hp + b0 * NP + p0 + pl);
                float2 h1c = *(const float2*)(g_hp + b1 * NP + p0 + pl);
                s0 += tanhf(acc[mt][nt][0] + h0c.x) * v2.x
                    + tanhf(acc[mt][nt][1] + h0c.y) * v2.y;
                s1 += tanhf(acc[mt][nt][2] + h1c.x) * v2.x
                    + tanhf(acc[mt][nt][3] + h1c.y) * v2.y;
            }
            s0 += __shfl_down_sync(0xffffffffu, s0, 2, 4);
            s0 += __shfl_down_sync(0xffffffffu, s0, 1, 4);
            s1 += __shfl_down_sync(0xffffffffu, s1, 2, 4);
            s1 += __shfl_down_sync(0xffffffffu, s1, 1, 4);
            if (qc == 0) {
                sh_red[wn * MT + row0]     = s0;
                sh_red[wn * MT + row0 + 8] = s1;
            }
        }
        __syncthreads();
        if (tid < MT)
            rowsum += sh_red[tid] + sh_red[MT + tid] + sh_red[2 * MT + tid]
                    + sh_red[3 * MT + tid];
        __syncthreads();   // sh_red safe to reuse next nb
    }

    if (tid < MT) {
        int grow = r0 + tid;
        int b = grow & 31;
        int s = grow >> 5;
        g_part[((size_t)ny * NB + b) * NS + s] = rowsum;
    }
}

// ---------------------------------------------------------------------------
// Kernel 3: logits = sum of 2 p-half partials; softmax over S per b.
// ---------------------------------------------------------------------------
__global__ void __launch_bounds__(256) softmax_kernel()
{
    int b = blockIdx.x;
    int tid = threadIdx.x;
    int lane = tid & 31, wid = tid >> 5;
    __shared__ float redm[8];
    __shared__ float reds[8];

    float vals[8];
    float m = -1e30f;
#pragma unroll
    for (int i = 0; i < 8; i++) {
        int s = tid + i * 256;
        float a = g_part[(size_t)b * NS + s] + g_part[((size_t)NB + b) * NS + s];
        vals[i] = a;
        m = fmaxf(m, a);
    }
#pragma unroll
    for (int off = 16; off; off >>= 1) m = fmaxf(m, __shfl_xor_sync(0xffffffffu, m, off));
    if (lane == 0) redm[wid] = m;
    __syncthreads();
    float bmax = redm[0];
#pragma unroll
    for (int w = 1; w < 8; w++) bmax = fmaxf(bmax, redm[w]);

    float ssum = 0.f;
#pragma unroll
    for (int i = 0; i < 8; i++) {
        vals[i] = expf(vals[i] - bmax);
        ssum += vals[i];
    }
#pragma unroll
    for (int off = 16; off; off >>= 1) ssum += __shfl_xor_sync(0xffffffffu, ssum, off);
    if (lane == 0) reds[wid] = ssum;
    __syncthreads();
    float tot = 0.f;
#pragma unroll
    for (int w = 0; w < 8; w++) tot += reds[w];
    float inv = 1.f / tot;

#pragma unroll
    for (int i = 0; i < 8; i++)
        g_att[b * NS + tid + i * 256] = vals[i] * inv;
}

// ---------------------------------------------------------------------------
// Kernel 4: weighted partials per (s-chunk of 128, b)
// ---------------------------------------------------------------------------
__global__ void __launch_bounds__(256) weighted_kernel(const float* __restrict__ enc)
{
    const int chunk = blockIdx.x;
    const int b = blockIdx.y;
    const int tid = threadIdx.x;

    __shared__ float aw[128];
    if (tid < 128) aw[tid] = g_att[b * NS + chunk * 128 + tid];
    __syncthreads();

    const float4* base = (const float4*)enc +
                         ((size_t)(chunk * 128) * NB + b) * (NE / 4) + tid;
    const size_t rowStride = (size_t)NB * NE / 4;

    float4 acc = make_float4(0.f, 0.f, 0.f, 0.f);
#pragma unroll 4
    for (int s = 0; s < 128; s++) {
        float w = aw[s];
        float4 x = base[(size_t)s * rowStride];
        acc.x += w * x.x; acc.y += w * x.y;
        acc.z += w * x.z; acc.w += w * x.w;
    }
    float4* o = (float4*)&g_wpart[((size_t)chunk * NB + b) * NE] + tid;
    *o = acc;
}

// ---------------------------------------------------------------------------
// Kernel 5: reduce 16 s-chunk partials -> out
// ---------------------------------------------------------------------------
__global__ void __launch_bounds__(256) reduce_kernel(float* __restrict__ out)
{
    int idx = blockIdx.x * 256 + threadIdx.x;
    float acc = 0.f;
#pragma unroll
    for (int c = 0; c < 16; c++)
        acc += g_wpart[(size_t)c * (NB * NE) + idx];
    out[idx] = acc;
}

// ---------------------------------------------------------------------------
extern "C" void kernel_launch(void* const* d_in, const int* in_sizes, int n_in,
                              void* d_out, int out_size)
{
    const float* hidden = (const float*)d_in[0];   // (32, 1024)
    const float* enc    = (const float*)d_in[1];   // (2048, 32, 1024)
    const float* attn_w = (const float*)d_in[2];   // (1024, 2048)
    const float* attn_b = (const float*)d_in[3];   // (1024,)
    const float* v      = (const float*)d_in[4];   // (1024,)
    float* out = (float*)d_out;                    // (32, 1024)

    cudaFuncSetAttribute(energy_hmma_kernel,
                         cudaFuncAttributeMaxDynamicSharedMemorySize, SM_DYN);

    setup_kernel<<<NP, 256>>>(hidden, attn_w, attn_b);
    convert_w_kernel<<<(NP * NE / 4) / 256, 256>>>(attn_w);
    convert_enc_kernel<<<(int)(((size_t)NS * NB * NE / 4) / 256), 256>>>(enc);
    energy_hmma_kernel<<<dim3(NROWS / MT, 2), 256, SM_DYN>>>(v);
    softmax_kernel<<<NB, 256>>>();
    weighted_kernel<<<dim3(16, NB), 256>>>(enc);
    reduce_kernel<<<(NB * NE) / 256, 256>>>(out);
}